// round 2
// baseline (speedup 1.0000x reference)
#include <cuda_runtime.h>
#include <math.h>

// Problem constants
#define H 256
#define H2 512
#define G 2048
#define E 262144
#define TILE 16
#define EPS 1e-5f

// ---------------- device scratch (no allocations allowed) ----------------
__device__ float g_film[G * H];              // per-graph film output
__device__ float g_x[(size_t)E * H];         // per-edge MLP output
__device__ float g_selsum[G * H];            // masked scatter sum
__device__ float g_cnt[G];                   // masked count per graph
__device__ float g_Pc[G * H];                // (current * lh_g_lo) @ lh_W1_lo
__device__ float g_cs[G];                    // sum(current row)
__device__ float g_csq[G];                   // sum(current row ^2)
__device__ float g_vg[H];                    // lh_g @ lh_W1 (512-dot per col)
__device__ float g_vb[H];                    // lh_b @ lh_W1 + lh_b1
__device__ float g_Wh[H * H];                // lh_g_hi[k] * lh_W1[256+k][j]
__device__ int   g_maskmode;                 // 0=int32 1=float32 2=int8/bool

// ---------------- helpers ----------------
__device__ __forceinline__ float gelu_f(float x) {
    return 0.5f * x * (1.0f + erff(x * 0.70710678118654752f));
}

__device__ __forceinline__ void warpReduce2(float &a, float &b) {
#pragma unroll
    for (int o = 16; o; o >>= 1) {
        a += __shfl_xor_sync(0xffffffffu, a, o);
        b += __shfl_xor_sync(0xffffffffu, b, o);
    }
}

// block of 256 threads
__device__ __forceinline__ void blockReduce2(float &a, float &b) {
    __shared__ float sa[8], sb[8];
    int lane = threadIdx.x & 31, wid = threadIdx.x >> 5;
    warpReduce2(a, b);
    if (lane == 0) { sa[wid] = a; sb[wid] = b; }
    __syncthreads();
    if (wid == 0) {
        a = (lane < 8) ? sa[lane] : 0.f;
        b = (lane < 8) ? sb[lane] : 0.f;
#pragma unroll
        for (int o = 4; o; o >>= 1) {
            a += __shfl_xor_sync(0xffffffffu, a, o);
            b += __shfl_xor_sync(0xffffffffu, b, o);
        }
        if (lane == 0) { sa[0] = a; sb[0] = b; }
    }
    __syncthreads();
    a = sa[0]; b = sb[0];
    __syncthreads();
}

__device__ __forceinline__ float mask_val(const void *p, int e, int mode) {
    if (mode == 0) return ((const int *)p)[e] != 0 ? 1.f : 0.f;
    if (mode == 1) return ((const float *)p)[e] != 0.f ? 1.f : 0.f;
    return ((const unsigned char *)p)[e] != 0 ? 1.f : 0.f;
}

// ---------------- K0: dtype sniff for selected_mask ----------------
__global__ void sniff_kernel(const void *mask) {
    const unsigned int *w = (const unsigned int *)mask;
    int i32ok = 1, f32ok = 1;
    // 4096 words = 16KB, safely within E bytes even for int8 storage
    for (int i = threadIdx.x; i < 4096; i += 256) {
        unsigned int x = w[i];
        if (x > 1u) i32ok = 0;
        float f = __uint_as_float(x);
        if (!(f == 0.f || f == 1.f)) f32ok = 0;
    }
    int all_i32 = __syncthreads_and(i32ok);
    int all_f32 = __syncthreads_and(f32ok);
    if (threadIdx.x == 0) g_maskmode = all_i32 ? 0 : (all_f32 ? 1 : 2);
}

// ---------------- K1: zero accumulators ----------------
__global__ void zero_kernel() {
    int i = blockIdx.x * blockDim.x + threadIdx.x;
    if (i < G * H) g_selsum[i] = 0.f;
    if (i < G) g_cnt[i] = 0.f;
}

// ---------------- K2: precompute vg, vb, Wh ----------------
__global__ void prep_kernel(const float *lh_g, const float *lh_b,
                            const float *lh_W1, const float *lh_b1) {
    int j = threadIdx.x;
    if (blockIdx.x == 0) {
        float a = 0.f, b = 0.f;
        for (int k = 0; k < H2; k++) {
            float w = lh_W1[k * H + j];
            a += lh_g[k] * w;
            b += lh_b[k] * w;
        }
        g_vg[j] = a;
        g_vb[j] = b + lh_b1[j];
    } else {
        int base = (blockIdx.x - 1) * 1024 + j;
#pragma unroll
        for (int t = 0; t < 4; t++) {
            int idx = base + t * 256;
            int k = idx >> 8;
            g_Wh[idx] = lh_g[H + k] * lh_W1[(H + k) * H + (idx & 255)];
        }
    }
}

// ---------------- K3: per-graph film ----------------
__global__ void film_kernel(const float *question, const float *qf_g,
                            const float *qf_b, const float *qf_W,
                            const float *qf_bias) {
    int g = blockIdx.x, j = threadIdx.x;
    __shared__ __align__(16) float xn[H];
    float q = question[g * H + j];
    float s = q, sq = q * q;
    blockReduce2(s, sq);
    float m = s * (1.f / H);
    float v = sq * (1.f / H) - m * m;
    float inv = rsqrtf(v + EPS);
    xn[j] = (q - m) * inv * qf_g[j] + qf_b[j];
    __syncthreads();
    float acc = qf_bias[j];
    for (int k = 0; k < H; k += 4) {
        float4 x4 = *reinterpret_cast<const float4 *>(&xn[k]);
        acc = fmaf(x4.x, qf_W[(k + 0) * H + j], acc);
        acc = fmaf(x4.y, qf_W[(k + 1) * H + j], acc);
        acc = fmaf(x4.z, qf_W[(k + 2) * H + j], acc);
        acc = fmaf(x4.w, qf_W[(k + 3) * H + j], acc);
    }
    g_film[g * H + j] = gelu_f(acc);
}

// ---------------- K4: per-edge 2-layer MLP + scatter ----------------
__global__ __launch_bounds__(256) void pass1_kernel(
    const float *edge_tokens, const float *order_emb, const float *type_emb,
    const float *mlp_g, const float *mlp_b, const float *mlp_W,
    const float *mlp_bias, const int *edge_batch, const int *sel_order,
    const void *mask) {
    __shared__ __align__(16) float A[TILE][H];
    __shared__ __align__(16) float B[TILE][H];
    __shared__ int sb[TILE];
    __shared__ int soi[TILE];
    __shared__ float smask[TILE];

    int tid = threadIdx.x;
    int e0 = blockIdx.x * TILE;
    int mode = g_maskmode;

    if (tid < TILE) {
        int e = e0 + tid;
        sb[tid] = edge_batch[e];
        int so = sel_order[e];
        so = so < -1 ? -1 : (so > 10 ? 10 : so);
        soi[tid] = so + 1;
        smask[tid] = mask_val(mask, e, mode);
    }
    __syncthreads();

    // build input rows: edge + order_emb + film + type_emb[2]
    for (int i = tid; i < TILE * H; i += 256) {
        int r = i >> 8, c = i & 255;
        int e = e0 + r;
        A[r][c] = edge_tokens[(size_t)e * H + c] + order_emb[soi[r] * H + c] +
                  g_film[sb[r] * H + c] + type_emb[2 * H + c];
    }
    __syncthreads();

    int warp = tid >> 5, lane = tid & 31;

#pragma unroll
    for (int layer = 0; layer < 2; layer++) {
        const float *gg = mlp_g + layer * H;
        const float *bb = mlp_b + layer * H;
        // LN rows A -> B
        for (int r = warp; r < TILE; r += 8) {
            float s = 0.f, sq = 0.f;
            for (int c = lane; c < H; c += 32) {
                float v = A[r][c];
                s += v; sq += v * v;
            }
            warpReduce2(s, sq);
            float m = s * (1.f / H);
            float var = sq * (1.f / H) - m * m;
            float inv = rsqrtf(var + EPS);
            for (int c = lane; c < H; c += 32)
                B[r][c] = (A[r][c] - m) * inv * gg[c] + bb[c];
        }
        __syncthreads();
        // matmul B @ W -> gelu -> A   (thread = output column)
        const float *W = mlp_W + layer * H * H;
        float bias = mlp_bias[layer * H + tid];
        float acc[TILE];
#pragma unroll
        for (int r = 0; r < TILE; r++) acc[r] = bias;
        for (int k = 0; k < H; k += 4) {
            float w0 = W[(k + 0) * H + tid];
            float w1 = W[(k + 1) * H + tid];
            float w2 = W[(k + 2) * H + tid];
            float w3 = W[(k + 3) * H + tid];
#pragma unroll
            for (int r = 0; r < TILE; r++) {
                float4 b4 = *reinterpret_cast<const float4 *>(&B[r][k]);
                acc[r] = fmaf(b4.x, w0, acc[r]);
                acc[r] = fmaf(b4.y, w1, acc[r]);
                acc[r] = fmaf(b4.z, w2, acc[r]);
                acc[r] = fmaf(b4.w, w3, acc[r]);
            }
        }
#pragma unroll
        for (int r = 0; r < TILE; r++) A[r][tid] = gelu_f(acc[r]);
        __syncthreads();
    }

    // write x
    for (int i = tid; i < TILE * H; i += 256) {
        int r = i >> 8, c = i & 255;
        g_x[(size_t)(e0 + r) * H + c] = A[r][c];
    }

    // masked scatter (sorted edge_batch -> run-length before atomics)
    {
        float accs = 0.f;
        int bprev = sb[0];
#pragma unroll
        for (int r = 0; r < TILE; r++) {
            int b = sb[r];
            if (b != bprev) {
                atomicAdd(&g_selsum[bprev * H + tid], accs);
                accs = 0.f;
                bprev = b;
            }
            accs += smask[r] * A[r][tid];
        }
        atomicAdd(&g_selsum[bprev * H + tid], accs);
    }
    if (tid == 0) {
        float c = 0.f;
        int bprev = sb[0];
#pragma unroll
        for (int r = 0; r < TILE; r++) {
            int b = sb[r];
            if (b != bprev) {
                atomicAdd(&g_cnt[bprev], c);
                c = 0.f;
                bprev = b;
            }
            c += smask[r];
        }
        atomicAdd(&g_cnt[bprev], c);
    }
}

// ---------------- K5: per-graph current + Pc + stop head ----------------
__global__ void graph_kernel(const float *question, const float *gn_g,
                             const float *gn_b, const float *lh_g,
                             const float *lh_W1, const float *sp_g,
                             const float *sp_b, const float *sp_W1,
                             const float *sp_b1, const float *sp_W2,
                             const float *sp_b2, float *out_stop,
                             float *out_cur) {
    int g = blockIdx.x, j = threadIdx.x;
    __shared__ __align__(16) float cg[H];
    __shared__ __align__(16) float zn[H2];

    float q = question[g * H + j];
    float cnt = g_cnt[g];
    float pre = g_selsum[g * H + j] / fmaxf(cnt, 1.f) + q;
    float s = pre, sq = pre * pre;
    blockReduce2(s, sq);
    float m = s * (1.f / H);
    float v = sq * (1.f / H) - m * m;
    float inv = rsqrtf(v + EPS);
    float cur = (pre - m) * inv * gn_g[j] + gn_b[j];
    cg[j] = cur * lh_g[j];
    out_cur[g * H + j] = cur;

    float cs = cur, csq = cur * cur;
    blockReduce2(cs, csq);
    if (j == 0) { g_cs[g] = cs; g_csq[g] = csq; }

    float qs = q, qsq = q * q;
    blockReduce2(qs, qsq);

    // 512-LN for stop head
    float m5 = (cs + qs) * (1.f / H2);
    float v5 = (csq + qsq) * (1.f / H2) - m5 * m5;
    float i5 = rsqrtf(v5 + EPS);
    zn[j] = (cur - m5) * i5 * sp_g[j] + sp_b[j];
    zn[H + j] = (q - m5) * i5 * sp_g[H + j] + sp_b[H + j];
    __syncthreads();

    // Pc[g][j] = sum_k (cur*lh_g)[k] * lh_W1[k][j]
    float acc = 0.f;
    for (int k = 0; k < H; k += 4) {
        float4 c4 = *reinterpret_cast<const float4 *>(&cg[k]);
        acc = fmaf(c4.x, lh_W1[(k + 0) * H + j], acc);
        acc = fmaf(c4.y, lh_W1[(k + 1) * H + j], acc);
        acc = fmaf(c4.z, lh_W1[(k + 2) * H + j], acc);
        acc = fmaf(c4.w, lh_W1[(k + 3) * H + j], acc);
    }
    g_Pc[g * H + j] = acc;

    // stop head
    float acc2 = sp_b1[j];
    for (int k = 0; k < H2; k += 4) {
        float4 z4 = *reinterpret_cast<const float4 *>(&zn[k]);
        acc2 = fmaf(z4.x, sp_W1[(k + 0) * H + j], acc2);
        acc2 = fmaf(z4.y, sp_W1[(k + 1) * H + j], acc2);
        acc2 = fmaf(z4.z, sp_W1[(k + 2) * H + j], acc2);
        acc2 = fmaf(z4.w, sp_W1[(k + 3) * H + j], acc2);
    }
    float contrib = gelu_f(acc2) * sp_W2[j];
    float dummy = 0.f;
    blockReduce2(contrib, dummy);
    if (j == 0) out_stop[g] = contrib + sp_b2[0];
}

// ---------------- K6: per-edge nxt + lookahead head ----------------
__global__ __launch_bounds__(256) void pass2_kernel(
    const float *question, const float *gn_g, const float *gn_b,
    const float *lh_W2, const float *lh_b2, const int *edge_batch,
    float *out_edge) {
    __shared__ __align__(16) float Bm[TILE][H];
    __shared__ int sb[TILE];
    __shared__ float rm[TILE], rinv[TILE];

    int tid = threadIdx.x;
    int e0 = blockIdx.x * TILE;
    if (tid < TILE) sb[tid] = edge_batch[e0 + tid];
    __syncthreads();

    int warp = tid >> 5, lane = tid & 31;
    for (int r = warp; r < TILE; r += 8) {
        int b = sb[r];
        float invc = 1.f / (g_cnt[b] + 1.f);
        float s = 0.f, sq = 0.f;
        for (int c = lane; c < H; c += 32) {
            float v = (g_selsum[b * H + c] + g_x[(size_t)(e0 + r) * H + c]) * invc +
                      question[b * H + c];
            Bm[r][c] = v;
            s += v; sq += v * v;
        }
        warpReduce2(s, sq);
        float m = s * (1.f / H);
        float var = sq * (1.f / H) - m * m;
        float inv = rsqrtf(var + EPS);
        float s2 = 0.f, sq2 = 0.f;
        for (int c = lane; c < H; c += 32) {
            float n = (Bm[r][c] - m) * inv * gn_g[c] + gn_b[c];
            Bm[r][c] = n;
            s2 += n; sq2 += n * n;
        }
        warpReduce2(s2, sq2);
        if (lane == 0) {
            float cs = g_cs[b], csq = g_csq[b];
            float M = (cs + s2) * (1.f / H2);
            float V = (csq + sq2) * (1.f / H2) - M * M;
            rm[r] = M;
            rinv[r] = rsqrtf(V + EPS);
        }
    }
    __syncthreads();

    // t = nxt @ Wh (g_hi folded in); then head epilogue
    float acc[TILE];
#pragma unroll
    for (int r = 0; r < TILE; r++) acc[r] = 0.f;
    for (int k = 0; k < H; k += 4) {
        float w0 = g_Wh[(k + 0) * H + tid];
        float w1 = g_Wh[(k + 1) * H + tid];
        float w2 = g_Wh[(k + 2) * H + tid];
        float w3 = g_Wh[(k + 3) * H + tid];
#pragma unroll
        for (int r = 0; r < TILE; r++) {
            float4 b4 = *reinterpret_cast<const float4 *>(&Bm[r][k]);
            acc[r] = fmaf(b4.x, w0, acc[r]);
            acc[r] = fmaf(b4.y, w1, acc[r]);
            acc[r] = fmaf(b4.z, w2, acc[r]);
            acc[r] = fmaf(b4.w, w3, acc[r]);
        }
    }

    float vgj = g_vg[tid], vbj = g_vb[tid], w2j = lh_W2[tid];
    float b2 = lh_b2[0];
#pragma unroll
    for (int r = 0; r < TILE; r++) {
        float hpre = (g_Pc[sb[r] * H + tid] + acc[r] - rm[r] * vgj) * rinv[r] + vbj;
        float contrib = gelu_f(hpre) * w2j;
        float dummy = 0.f;
        blockReduce2(contrib, dummy);
        if (tid == 0) out_edge[e0 + r] = contrib + b2;
    }
}

// ---------------- launch ----------------
extern "C" void kernel_launch(void *const *d_in, const int *in_sizes, int n_in,
                              void *d_out, int out_size) {
    const float *edge_tokens = (const float *)d_in[0];
    const float *question    = (const float *)d_in[1];
    const float *order_emb   = (const float *)d_in[2];
    const float *type_emb    = (const float *)d_in[3];
    const float *gn_g = (const float *)d_in[4];
    const float *gn_b = (const float *)d_in[5];
    const float *qf_g = (const float *)d_in[6];
    const float *qf_b = (const float *)d_in[7];
    const float *qf_W = (const float *)d_in[8];
    const float *qf_bias = (const float *)d_in[9];
    const float *mlp_g = (const float *)d_in[10];
    const float *mlp_b = (const float *)d_in[11];
    const float *mlp_W = (const float *)d_in[12];
    const float *mlp_bias = (const float *)d_in[13];
    const float *lh_g = (const float *)d_in[14];
    const float *lh_b = (const float *)d_in[15];
    const float *lh_W1 = (const float *)d_in[16];
    const float *lh_b1 = (const float *)d_in[17];
    const float *lh_W2 = (const float *)d_in[18];
    const float *lh_b2 = (const float *)d_in[19];
    const float *sp_g = (const float *)d_in[20];
    const float *sp_b = (const float *)d_in[21];
    const float *sp_W1 = (const float *)d_in[22];
    const float *sp_b1 = (const float *)d_in[23];
    const float *sp_W2 = (const float *)d_in[24];
    const float *sp_b2 = (const float *)d_in[25];
    const int *edge_batch = (const int *)d_in[26];
    const void *sel_mask = (const void *)d_in[27];
    const int *sel_order = (const int *)d_in[28];

    float *out_edge = (float *)d_out;
    float *out_stop = out_edge + E;
    float *out_cur = out_stop + G;

    sniff_kernel<<<1, 256>>>(sel_mask);
    zero_kernel<<<(G * H + 255) / 256, 256>>>();
    prep_kernel<<<65, 256>>>(lh_g, lh_b, lh_W1, lh_b1);
    film_kernel<<<G, 256>>>(question, qf_g, qf_b, qf_W, qf_bias);
    pass1_kernel<<<E / TILE, 256>>>(edge_tokens, order_emb, type_emb, mlp_g,
                                    mlp_b, mlp_W, mlp_bias, edge_batch,
                                    sel_order, sel_mask);
    graph_kernel<<<G, 256>>>(question, gn_g, gn_b, lh_g, lh_W1, sp_g, sp_b,
                             sp_W1, sp_b1, sp_W2, sp_b2, out_stop, out_cur);
    pass2_kernel<<<E / TILE, 256>>>(question, gn_g, gn_b, lh_W2, lh_b2,
                                    edge_batch, out_edge);
}

// round 4
// speedup vs baseline: 3.4901x; 3.4901x over previous
#include <cuda_runtime.h>
#include <cuda_fp16.h>
#include <stdint.h>
#include <cstdint>
#include <math.h>

// Problem constants
#define H 256
#define H2 512
#define G 2048
#define E 262144
#define EPS 1e-5f
#define MT 64      // edge rows per mma block
#define PA 264     // padded row stride (halves) for smem tiles

// ---------------- device scratch ----------------
__device__ float g_film[G * H];
__device__ __half g_xh[(size_t)E * H];       // MLP output (fp16)
__device__ float g_selsum[G * H];
__device__ float g_cnt[G];
__device__ float g_Pc[G * H];
__device__ float g_cs[G];
__device__ float g_csq[G];
__device__ float g_vg[H];
__device__ float g_vb[H];
__device__ __align__(16) __half hW[2 * H * H];   // fp16 mlp weights
__device__ __align__(16) __half hWh[H * H];      // fp16 (lh_g_hi * lh_W1_hi)
__device__ int g_maskmode;

// ---------------- helpers ----------------
__device__ __forceinline__ float gelu_f(float x) {
    return 0.5f * x * (1.0f + erff(x * 0.70710678118654752f));
}

__device__ __forceinline__ void warpReduce2(float &a, float &b) {
#pragma unroll
    for (int o = 16; o; o >>= 1) {
        a += __shfl_xor_sync(0xffffffffu, a, o);
        b += __shfl_xor_sync(0xffffffffu, b, o);
    }
}

__device__ __forceinline__ void blockReduce2(float &a, float &b) {
    __shared__ float sa[8], sb_[8];
    int lane = threadIdx.x & 31, wid = threadIdx.x >> 5;
    warpReduce2(a, b);
    if (lane == 0) { sa[wid] = a; sb_[wid] = b; }
    __syncthreads();
    if (wid == 0) {
        a = (lane < 8) ? sa[lane] : 0.f;
        b = (lane < 8) ? sb_[lane] : 0.f;
#pragma unroll
        for (int o = 4; o; o >>= 1) {
            a += __shfl_xor_sync(0xffffffffu, a, o);
            b += __shfl_xor_sync(0xffffffffu, b, o);
        }
        if (lane == 0) { sa[0] = a; sb_[0] = b; }
    }
    __syncthreads();
    a = sa[0]; b = sb_[0];
    __syncthreads();
}

__device__ __forceinline__ float mask_val(const void *p, int e, int mode) {
    if (mode == 0) return ((const int *)p)[e] != 0 ? 1.f : 0.f;
    if (mode == 1) return ((const float *)p)[e] != 0.f ? 1.f : 0.f;
    return ((const unsigned char *)p)[e] != 0 ? 1.f : 0.f;
}

__device__ __forceinline__ unsigned int s2u(const void *p) {
    return (unsigned int)__cvta_generic_to_shared(p);
}

__device__ __forceinline__ void ldm_x4(unsigned int &r0, unsigned int &r1,
                                       unsigned int &r2, unsigned int &r3,
                                       unsigned int addr) {
    asm volatile("ldmatrix.sync.aligned.m8n8.x4.shared.b16 {%0,%1,%2,%3}, [%4];"
                 : "=r"(r0), "=r"(r1), "=r"(r2), "=r"(r3) : "r"(addr));
}
__device__ __forceinline__ void ldm_x4_t(unsigned int &r0, unsigned int &r1,
                                         unsigned int &r2, unsigned int &r3,
                                         unsigned int addr) {
    asm volatile("ldmatrix.sync.aligned.m8n8.x4.trans.shared.b16 {%0,%1,%2,%3}, [%4];"
                 : "=r"(r0), "=r"(r1), "=r"(r2), "=r"(r3) : "r"(addr));
}
__device__ __forceinline__ void mma16816(float *c, unsigned int a0,
                                         unsigned int a1, unsigned int a2,
                                         unsigned int a3, unsigned int b0,
                                         unsigned int b1) {
    asm volatile(
        "mma.sync.aligned.m16n8k16.row.col.f32.f16.f16.f32 "
        "{%0,%1,%2,%3}, {%4,%5,%6,%7}, {%8,%9}, {%0,%1,%2,%3};"
        : "+f"(c[0]), "+f"(c[1]), "+f"(c[2]), "+f"(c[3])
        : "r"(a0), "r"(a1), "r"(a2), "r"(a3), "r"(b0), "r"(b1));
}

// ---------------- K0: dtype sniff ----------------
__global__ void sniff_kernel(const void *mask) {
    const unsigned int *w = (const unsigned int *)mask;
    int i32ok = 1, f32ok = 1;
    for (int i = threadIdx.x; i < 4096; i += 256) {
        unsigned int x = w[i];
        if (x > 1u) i32ok = 0;
        float f = __uint_as_float(x);
        if (!(f == 0.f || f == 1.f)) f32ok = 0;
    }
    int all_i32 = __syncthreads_and(i32ok);
    int all_f32 = __syncthreads_and(f32ok);
    if (threadIdx.x == 0) g_maskmode = all_i32 ? 0 : (all_f32 ? 1 : 2);
}

// ---------------- K1: zero accumulators ----------------
__global__ void zero_kernel() {
    int i = blockIdx.x * blockDim.x + threadIdx.x;
    if (i < G * H) g_selsum[i] = 0.f;
    if (i < G) g_cnt[i] = 0.f;
}

// ---------------- K2a: vg / vb ----------------
__global__ void prep_kernel(const float *lh_g, const float *lh_b,
                            const float *lh_W1, const float *lh_b1) {
    int j = threadIdx.x;
    float a = 0.f, b = 0.f;
    for (int k = 0; k < H2; k++) {
        float w = lh_W1[k * H + j];
        a += lh_g[k] * w;
        b += lh_b[k] * w;
    }
    g_vg[j] = a;
    g_vb[j] = b + lh_b1[j];
}

// ---------------- K2b: fp16 weights ----------------
__global__ void prep_half(const float *mlp_W, const float *lh_g,
                          const float *lh_W1) {
    int i = blockIdx.x * blockDim.x + threadIdx.x;  // 0 .. 3*65536
    if (i < 2 * H * H) {
        hW[i] = __float2half(mlp_W[i]);
    } else {
        int j = i - 2 * H * H;
        int k = j >> 8;
        hWh[j] = __float2half(lh_g[H + k] * lh_W1[(H + k) * H + (j & 255)]);
    }
}

// ---------------- K3: per-graph film ----------------
__global__ void film_kernel(const float *question, const float *qf_g,
                            const float *qf_b, const float *qf_W,
                            const float *qf_bias) {
    int g = blockIdx.x, j = threadIdx.x;
    __shared__ __align__(16) float xn[H];
    float q = question[g * H + j];
    float s = q, sq = q * q;
    blockReduce2(s, sq);
    float m = s * (1.f / H);
    float v = sq * (1.f / H) - m * m;
    float inv = rsqrtf(v + EPS);
    xn[j] = (q - m) * inv * qf_g[j] + qf_b[j];
    __syncthreads();
    float acc = qf_bias[j];
    for (int k = 0; k < H; k += 4) {
        float4 x4 = *reinterpret_cast<const float4 *>(&xn[k]);
        acc = fmaf(x4.x, qf_W[(k + 0) * H + j], acc);
        acc = fmaf(x4.y, qf_W[(k + 1) * H + j], acc);
        acc = fmaf(x4.z, qf_W[(k + 2) * H + j], acc);
        acc = fmaf(x4.w, qf_W[(k + 3) * H + j], acc);
    }
    g_film[g * H + j] = gelu_f(acc);
}

// ---------------- K4: pass1 — 2-layer MLP via HMMA + scatter ----------------
extern __shared__ __align__(16) char dynsmem[];

__global__ __launch_bounds__(256) void pass1_mma(
    const float *edge_tokens, const float *order_emb, const float *type_emb,
    const float *mlp_g, const float *mlp_b, const float *mlp_bias,
    const int *edge_batch, const int *sel_order, const void *mask) {
    __half *Ash = (__half *)dynsmem;                      // [64][PA]
    __half *Bsh = (__half *)(dynsmem + MT * PA * 2);      // [2][16][PA]
    float *Xs = (float *)dynsmem;                         // [64][256] alias

    __shared__ float p_g0[H], p_b0[H], p_g1[H], p_b1[H];
    __shared__ float p_bias0[H], p_bias1[H], p_typ[H];
    __shared__ int sb[MT], soi_[MT];
    __shared__ float smask_[MT];
    __shared__ float sS[MT], sQ[MT], sM[MT], sI[MT];

    int tid = threadIdx.x, lane = tid & 31, warp = tid >> 5;
    int wm = warp >> 1, wn = warp & 1;
    int e0 = blockIdx.x * MT;
    int mode = g_maskmode;

    p_g0[tid] = mlp_g[tid];      p_b0[tid] = mlp_b[tid];
    p_g1[tid] = mlp_g[H + tid];  p_b1[tid] = mlp_b[H + tid];
    p_bias0[tid] = mlp_bias[tid];
    p_bias1[tid] = mlp_bias[H + tid];
    p_typ[tid] = type_emb[2 * H + tid];
    if (tid < MT) {
        int e = e0 + tid;
        sb[tid] = edge_batch[e];
        int so = sel_order[e];
        so = so < -1 ? -1 : (so > 10 ? 10 : so);
        soi_[tid] = so + 1;
        smask_[tid] = mask_val(mask, e, mode);
    }
    __syncthreads();

    // ---- build LN(layer-1 input) into Ash (fp16) ----
    for (int rr = 0; rr < 8; rr++) {
        int r = warp * 8 + rr;
        int e = e0 + r, b = sb[r];
        const float *et = &edge_tokens[(size_t)e * H];
        const float *fl = &g_film[b * H];
        const float *oe = &order_emb[soi_[r] * H];
        float v[8], s = 0.f, sq = 0.f;
#pragma unroll
        for (int i = 0; i < 8; i++) {
            int c = lane + 32 * i;
            float x = et[c] + oe[c] + fl[c] + p_typ[c];
            v[i] = x; s += x; sq += x * x;
        }
        warpReduce2(s, sq);
        float m = s * (1.f / H);
        float inv = rsqrtf(sq * (1.f / H) - m * m + EPS);
#pragma unroll
        for (int i = 0; i < 8; i++) {
            int c = lane + 32 * i;
            Ash[r * PA + c] = __float2half((v[i] - m) * inv * p_g0[c] + p_b0[c]);
        }
    }
    __syncthreads();

    int r0 = 16 * wm + (lane >> 2);
    int r1 = r0 + 8;
    int cbase0 = 128 * wn + 2 * (lane & 3);

    float acc[16][4];

#pragma unroll 1
    for (int layer = 0; layer < 2; layer++) {
        const __half *Wl = hW + layer * H * H;
        const float *bias = layer ? p_bias1 : p_bias0;
#pragma unroll
        for (int t = 0; t < 16; t++) {
            int c = cbase0 + 8 * t;
            acc[t][0] = bias[c];     acc[t][1] = bias[c + 1];
            acc[t][2] = bias[c];     acc[t][3] = bias[c + 1];
        }
        // preload k-chunk 0
        {
            const uint4 *src = (const uint4 *)(Wl + tid * 16);
            uint4 q0 = src[0], q1 = src[1];
            uint4 *dst = (uint4 *)(Bsh + (tid >> 4) * PA + (tid & 15) * 16);
            dst[0] = q0; dst[1] = q1;
        }
        __syncthreads();

        for (int ks = 0; ks < 16; ks++) {
            uint4 q0, q1;
            if (ks < 15) {
                const uint4 *src = (const uint4 *)(Wl + (ks + 1) * 16 * H + tid * 16);
                q0 = src[0]; q1 = src[1];
            }
            __half *Bb = Bsh + (ks & 1) * 16 * PA;
            unsigned int a0, a1, a2, a3;
            ldm_x4(a0, a1, a2, a3,
                   s2u(Ash + (16 * wm + (lane & 15)) * PA + ks * 16 + (lane >> 4) * 8));
#pragma unroll
            for (int t2 = 0; t2 < 8; t2++) {
                unsigned int b0, b1, b2, b3;
                ldm_x4_t(b0, b1, b2, b3,
                         s2u(Bb + (lane & 15) * PA + 128 * wn + 16 * t2 + (lane >> 4) * 8));
                mma16816(acc[2 * t2], a0, a1, a2, a3, b0, b1);
                mma16816(acc[2 * t2 + 1], a0, a1, a2, a3, b2, b3);
            }
            if (ks < 15) {
                __half *Bn = Bsh + ((ks + 1) & 1) * 16 * PA;
                uint4 *dst = (uint4 *)(Bn + (tid >> 4) * PA + (tid & 15) * 16);
                dst[0] = q0; dst[1] = q1;
            }
            __syncthreads();
        }

        // ---- epilogue: gelu (+ LN to fp16 for layer 0) ----
        if (layer == 0) {
            if (tid < MT) { sS[tid] = 0.f; sQ[tid] = 0.f; }
            __syncthreads();
            float s0 = 0.f, q0s = 0.f, s1 = 0.f, q1s = 0.f;
#pragma unroll
            for (int t = 0; t < 16; t++) {
                acc[t][0] = gelu_f(acc[t][0]); acc[t][1] = gelu_f(acc[t][1]);
                acc[t][2] = gelu_f(acc[t][2]); acc[t][3] = gelu_f(acc[t][3]);
                s0 += acc[t][0] + acc[t][1]; q0s += acc[t][0] * acc[t][0] + acc[t][1] * acc[t][1];
                s1 += acc[t][2] + acc[t][3]; q1s += acc[t][2] * acc[t][2] + acc[t][3] * acc[t][3];
            }
            s0 += __shfl_xor_sync(0xffffffffu, s0, 1); s0 += __shfl_xor_sync(0xffffffffu, s0, 2);
            q0s += __shfl_xor_sync(0xffffffffu, q0s, 1); q0s += __shfl_xor_sync(0xffffffffu, q0s, 2);
            s1 += __shfl_xor_sync(0xffffffffu, s1, 1); s1 += __shfl_xor_sync(0xffffffffu, s1, 2);
            q1s += __shfl_xor_sync(0xffffffffu, q1s, 1); q1s += __shfl_xor_sync(0xffffffffu, q1s, 2);
            if ((lane & 3) == 0) {
                atomicAdd(&sS[r0], s0); atomicAdd(&sQ[r0], q0s);
                atomicAdd(&sS[r1], s1); atomicAdd(&sQ[r1], q1s);
            }
            __syncthreads();
            if (tid < MT) {
                float m = sS[tid] * (1.f / H);
                sM[tid] = m;
                sI[tid] = rsqrtf(sQ[tid] * (1.f / H) - m * m + EPS);
            }
            __syncthreads();
            float m0 = sM[r0], i0 = sI[r0], m1 = sM[r1], i1 = sI[r1];
#pragma unroll
            for (int t = 0; t < 16; t++) {
                int c = cbase0 + 8 * t;
                float n00 = (acc[t][0] - m0) * i0 * p_g1[c] + p_b1[c];
                float n01 = (acc[t][1] - m0) * i0 * p_g1[c + 1] + p_b1[c + 1];
                float n10 = (acc[t][2] - m1) * i1 * p_g1[c] + p_b1[c];
                float n11 = (acc[t][3] - m1) * i1 * p_g1[c + 1] + p_b1[c + 1];
                *(__half2 *)&Ash[r0 * PA + c] = __floats2half2_rn(n00, n01);
                *(__half2 *)&Ash[r1 * PA + c] = __floats2half2_rn(n10, n11);
            }
            __syncthreads();
        } else {
            // final: x = gelu(acc) -> Xs (aliased; all mma reads are done)
#pragma unroll
            for (int t = 0; t < 16; t++) {
                int c = cbase0 + 8 * t;
                Xs[r0 * H + c] = gelu_f(acc[t][0]);
                Xs[r0 * H + c + 1] = gelu_f(acc[t][1]);
                Xs[r1 * H + c] = gelu_f(acc[t][2]);
                Xs[r1 * H + c + 1] = gelu_f(acc[t][3]);
            }
            __syncthreads();
        }
    }

    // ---- write g_xh (fp16) ----
    for (int idx = tid; idx < MT * H; idx += 256) {
        int r = idx >> 8, c = idx & 255;
        g_xh[(size_t)(e0 + r) * H + c] = __float2half(Xs[r * H + c]);
    }

    // ---- masked scatter (sorted -> run-length) ----
    {
        float accs = 0.f;
        int bprev = sb[0];
        for (int r = 0; r < MT; r++) {
            int b = sb[r];
            if (b != bprev) {
                atomicAdd(&g_selsum[bprev * H + tid], accs);
                accs = 0.f;
                bprev = b;
            }
            accs += smask_[r] * Xs[r * H + tid];
        }
        atomicAdd(&g_selsum[bprev * H + tid], accs);
    }
    if (tid == 0) {
        float c = 0.f;
        int bprev = sb[0];
        for (int r = 0; r < MT; r++) {
            int b = sb[r];
            if (b != bprev) {
                atomicAdd(&g_cnt[bprev], c);
                c = 0.f;
                bprev = b;
            }
            c += smask_[r];
        }
        atomicAdd(&g_cnt[bprev], c);
    }
}

// ---------------- K5: per-graph current + Pc + stop head ----------------
__global__ void graph_kernel(const float *question, const float *gn_g,
                             const float *gn_b, const float *lh_g,
                             const float *lh_W1, const float *sp_g,
                             const float *sp_b, const float *sp_W1,
                             const float *sp_b1, const float *sp_W2,
                             const float *sp_b2, float *out_stop,
                             float *out_cur) {
    int g = blockIdx.x, j = threadIdx.x;
    __shared__ __align__(16) float cg[H];
    __shared__ __align__(16) float zn[H2];

    float q = question[g * H + j];
    float cnt = g_cnt[g];
    float pre = g_selsum[g * H + j] / fmaxf(cnt, 1.f) + q;
    float s = pre, sq = pre * pre;
    blockReduce2(s, sq);
    float m = s * (1.f / H);
    float v = sq * (1.f / H) - m * m;
    float inv = rsqrtf(v + EPS);
    float cur = (pre - m) * inv * gn_g[j] + gn_b[j];
    cg[j] = cur * lh_g[j];
    out_cur[g * H + j] = cur;

    float cs = cur, csq = cur * cur;
    blockReduce2(cs, csq);
    if (j == 0) { g_cs[g] = cs; g_csq[g] = csq; }

    float qs = q, qsq = q * q;
    blockReduce2(qs, qsq);

    float m5 = (cs + qs) * (1.f / H2);
    float v5 = (csq + qsq) * (1.f / H2) - m5 * m5;
    float i5 = rsqrtf(v5 + EPS);
    zn[j] = (cur - m5) * i5 * sp_g[j] + sp_b[j];
    zn[H + j] = (q - m5) * i5 * sp_g[H + j] + sp_b[H + j];
    __syncthreads();

    float acc = 0.f;
    for (int k = 0; k < H; k += 4) {
        float4 c4 = *reinterpret_cast<const float4 *>(&cg[k]);
        acc = fmaf(c4.x, lh_W1[(k + 0) * H + j], acc);
        acc = fmaf(c4.y, lh_W1[(k + 1) * H + j], acc);
        acc = fmaf(c4.z, lh_W1[(k + 2) * H + j], acc);
        acc = fmaf(c4.w, lh_W1[(k + 3) * H + j], acc);
    }
    g_Pc[g * H + j] = acc;

    float acc2 = sp_b1[j];
    for (int k = 0; k < H2; k += 4) {
        float4 z4 = *reinterpret_cast<const float4 *>(&zn[k]);
        acc2 = fmaf(z4.x, sp_W1[(k + 0) * H + j], acc2);
        acc2 = fmaf(z4.y, sp_W1[(k + 1) * H + j], acc2);
        acc2 = fmaf(z4.z, sp_W1[(k + 2) * H + j], acc2);
        acc2 = fmaf(z4.w, sp_W1[(k + 3) * H + j], acc2);
    }
    float contrib = gelu_f(acc2) * sp_W2[j];
    float dummy = 0.f;
    blockReduce2(contrib, dummy);
    if (j == 0) out_stop[g] = contrib + sp_b2[0];
}

// ---------------- K6: pass2 — nxt + lookahead head via HMMA ----------------
__global__ __launch_bounds__(256) void pass2_mma(
    const float *question, const float *gn_g, const float *gn_b,
    const float *lh_W2, const float *lh_b2, const int *edge_batch,
    float *out_edge) {
    __half *Ash = (__half *)dynsmem;                  // [64][PA]
    __half *Bsh = (__half *)(dynsmem + MT * PA * 2);  // [2][16][PA]

    __shared__ float sg[H], sbt[H], svg[H], svb[H], sw2[H];
    __shared__ int sb[MT];
    __shared__ float srm[MT], sri[MT], srow[MT];

    int tid = threadIdx.x, lane = tid & 31, warp = tid >> 5;
    int wm = warp >> 1, wn = warp & 1;
    int e0 = blockIdx.x * MT;

    sg[tid] = gn_g[tid]; sbt[tid] = gn_b[tid];
    svg[tid] = g_vg[tid]; svb[tid] = g_vb[tid]; sw2[tid] = lh_W2[tid];
    if (tid < MT) {
        sb[tid] = edge_batch[e0 + tid];
        srow[tid] = 0.f;
    }
    __syncthreads();

    // ---- build LN(nxt) into Ash fp16, compute rm/rinv ----
    for (int rr = 0; rr < 8; rr++) {
        int r = warp * 8 + rr;
        int b = sb[r];
        float invc = 1.f / (g_cnt[b] + 1.f);
        const float *ss = &g_selsum[b * H];
        const __half *xh = &g_xh[(size_t)(e0 + r) * H];
        const float *q = &question[b * H];
        float v[8], s = 0.f, sq = 0.f;
#pragma unroll
        for (int i = 0; i < 8; i++) {
            int c = lane + 32 * i;
            float x = (ss[c] + __half2float(xh[c])) * invc + q[c];
            v[i] = x; s += x; sq += x * x;
        }
        warpReduce2(s, sq);
        float m = s * (1.f / H);
        float inv = rsqrtf(sq * (1.f / H) - m * m + EPS);
        float s2 = 0.f, sq2 = 0.f;
#pragma unroll
        for (int i = 0; i < 8; i++) {
            int c = lane + 32 * i;
            float n = (v[i] - m) * inv * sg[c] + sbt[c];
            Ash[r * PA + c] = __float2half(n);
            s2 += n; sq2 += n * n;
        }
        warpReduce2(s2, sq2);
        if (lane == 0) {
            float cs = g_cs[b], csq = g_csq[b];
            float M = (cs + s2) * (1.f / H2);
            float V = (csq + sq2) * (1.f / H2) - M * M;
            srm[r] = M;
            sri[r] = rsqrtf(V + EPS);
        }
    }
    __syncthreads();

    // ---- matmul t = nxt @ Wh ----
    float acc[16][4];
#pragma unroll
    for (int t = 0; t < 16; t++)
        acc[t][0] = acc[t][1] = acc[t][2] = acc[t][3] = 0.f;

    {
        const uint4 *src = (const uint4 *)(hWh + tid * 16);
        uint4 q0 = src[0], q1 = src[1];
        uint4 *dst = (uint4 *)(Bsh + (tid >> 4) * PA + (tid & 15) * 16);
        dst[0] = q0; dst[1] = q1;
    }
    __syncthreads();

    for (int ks = 0; ks < 16; ks++) {
        uint4 q0, q1;
        if (ks < 15) {
            const uint4 *src = (const uint4 *)(hWh + (ks + 1) * 16 * H + tid * 16);
            q0 = src[0]; q1 = src[1];
        }
        __half *Bb = Bsh + (ks & 1) * 16 * PA;
        unsigned int a0, a1, a2, a3;
        ldm_x4(a0, a1, a2, a3,
               s2u(Ash + (16 * wm + (lane & 15)) * PA + ks * 16 + (lane >> 4) * 8));
#pragma unroll
        for (int t2 = 0; t2 < 8; t2++) {
            unsigned int b0, b1, b2, b3;
            ldm_x4_t(b0, b1, b2, b3,
                     s2u(Bb + (lane & 15) * PA + 128 * wn + 16 * t2 + (lane >> 4) * 8));
            mma16816(acc[2 * t2], a0, a1, a2, a3, b0, b1);
            mma16816(acc[2 * t2 + 1], a0, a1, a2, a3, b2, b3);
        }
        if (ks < 15) {
            __half *Bn = Bsh + ((ks + 1) & 1) * 16 * PA;
            uint4 *dst = (uint4 *)(Bn + (tid >> 4) * PA + (tid & 15) * 16);
            dst[0] = q0; dst[1] = q1;
        }
        __syncthreads();
    }

    // ---- epilogue: h = gelu((Pc + t - rm*vg)*rinv + vb); logits = h @ w2 ----
    int r0 = 16 * wm + (lane >> 2);
    int r1 = r0 + 8;
    int cbase0 = 128 * wn + 2 * (lane & 3);
    float rm0 = srm[r0], ri0 = sri[r0], rm1 = srm[r1], ri1 = sri[r1];
    int b0g = sb[r0], b1g = sb[r1];
    float sum0 = 0.f, sum1 = 0.f;
#pragma unroll
    for (int t = 0; t < 16; t++) {
        int c = cbase0 + 8 * t;
        float2 pc0 = *(const float2 *)&g_Pc[b0g * H + c];
        float2 pc1 = *(const float2 *)&g_Pc[b1g * H + c];
        float h00 = (pc0.x + acc[t][0] - rm0 * svg[c]) * ri0 + svb[c];
        float h01 = (pc0.y + acc[t][1] - rm0 * svg[c + 1]) * ri0 + svb[c + 1];
        float h10 = (pc1.x + acc[t][2] - rm1 * svg[c]) * ri1 + svb[c];
        float h11 = (pc1.y + acc[t][3] - rm1 * svg[c + 1]) * ri1 + svb[c + 1];
        sum0 += gelu_f(h00) * sw2[c] + gelu_f(h01) * sw2[c + 1];
        sum1 += gelu_f(h10) * sw2[c] + gelu_f(h11) * sw2[c + 1];
    }
    sum0 += __shfl_xor_sync(0xffffffffu, sum0, 1);
    sum0 += __shfl_xor_sync(0xffffffffu, sum0, 2);
    sum1 += __shfl_xor_sync(0xffffffffu, sum1, 1);
    sum1 += __shfl_xor_sync(0xffffffffu, sum1, 2);
    if ((lane & 3) == 0) {
        atomicAdd(&srow[r0], sum0);
        atomicAdd(&srow[r1], sum1);
    }
    __syncthreads();
    if (tid < MT) out_edge[e0 + tid] = srow[tid] + lh_b2[0];
}

// ---------------- launch ----------------
extern "C" void kernel_launch(void *const *d_in, const int *in_sizes, int n_in,
                              void *d_out, int out_size) {
    const float *edge_tokens = (const float *)d_in[0];
    const float *question = (const float *)d_in[1];
    const float *order_emb = (const float *)d_in[2];
    const float *type_emb = (const float *)d_in[3];
    const float *gn_g = (const float *)d_in[4];
    const float *gn_b = (const float *)d_in[5];
    const float *qf_g = (const float *)d_in[6];
    const float *qf_b = (const float *)d_in[7];
    const float *qf_W = (const float *)d_in[8];
    const float *qf_bias = (const float *)d_in[9];
    const float *mlp_g = (const float *)d_in[10];
    const float *mlp_b = (const float *)d_in[11];
    const float *mlp_W = (const float *)d_in[12];
    const float *mlp_bias = (const float *)d_in[13];
    const float *lh_g = (const float *)d_in[14];
    const float *lh_b = (const float *)d_in[15];
    const float *lh_W1 = (const float *)d_in[16];
    const float *lh_b1 = (const float *)d_in[17];
    const float *lh_W2 = (const float *)d_in[18];
    const float *lh_b2 = (const float *)d_in[19];
    const float *sp_g = (const float *)d_in[20];
    const float *sp_b = (const float *)d_in[21];
    const float *sp_W1 = (const float *)d_in[22];
    const float *sp_b1 = (const float *)d_in[23];
    const float *sp_W2 = (const float *)d_in[24];
    const float *sp_b2 = (const float *)d_in[25];
    const int *edge_batch = (const int *)d_in[26];
    const void *sel_mask = (const void *)d_in[27];
    const int *sel_order = (const int *)d_in[28];

    float *out_edge = (float *)d_out;
    float *out_stop = out_edge + E;
    float *out_cur = out_stop + G;

    const int SMEM1 = MT * H * 4;                      // 65536 (X alias is max)
    const int SMEM2 = MT * PA * 2 + 2 * 16 * PA * 2;   // 50688

    cudaFuncSetAttribute(pass1_mma, cudaFuncAttributeMaxDynamicSharedMemorySize, SMEM1);
    cudaFuncSetAttribute(pass2_mma, cudaFuncAttributeMaxDynamicSharedMemorySize, SMEM2);

    sniff_kernel<<<1, 256>>>(sel_mask);
    zero_kernel<<<(G * H + 255) / 256, 256>>>();
    prep_kernel<<<1, 256>>>(lh_g, lh_b, lh_W1, lh_b1);
    prep_half<<<(3 * H * H) / 256, 256>>>(mlp_W, lh_g, lh_W1);
    film_kernel<<<G, 256>>>(question, qf_g, qf_b, qf_W, qf_bias);
    pass1_mma<<<E / MT, 256, SMEM1>>>(edge_tokens, order_emb, type_emb, mlp_g,
                                      mlp_b, mlp_bias, edge_batch, sel_order,
                                      sel_mask);
    graph_kernel<<<G, 256>>>(question, gn_g, gn_b, lh_g, lh_W1, sp_g, sp_b,
                             sp_W1, sp_b1, sp_W2, sp_b2, out_stop, out_cur);
    pass2_mma<<<E / MT, 256, SMEM2>>>(question, gn_g, gn_b, lh_W2, lh_b2,
                                      edge_batch, out_edge);
}